// round 4
// baseline (speedup 1.0000x reference)
#include <cuda_runtime.h>

// ---------------------------------------------------------------------------
// VQ-EMA layer, GB300 (sm_103a)  — round 3
// Inputs : x [16,1024,256] f32, embed_w [1024,256] f32,
//          ema_cluster_size [1024] f32, ema_w [1024,256] f32
// Output : concat( quantized[16*1024*256], loss[1], embed_new[1024*256],
//                  cs[1024], ema_w_new[1024*256] )
// ---------------------------------------------------------------------------

constexpr int Bc = 16, Tc = 1024, Dc = 256, Kc = 1024;
constexpr int Nrows = Bc * Tc;            // 16384
constexpr int TM = 128;                   // rows per block
constexpr int TK = 32;                    // codebook cols per chunk
constexpr int NCHUNKS = Kc / TK;          // 32

constexpr float DECAYF = 0.99f;
constexpr float OMDF   = 0.01f;
constexpr float EPSF   = 1e-5f;
constexpr float KEPSF  = 0.01024f;        // K * EPS

// smem layout (words) for argmin kernel
constexpr int SX_STRIDE = 516;            // words per row-pair (2*256 + 4 pad, %4==0 for LDS.128)
constexpr int SX_WORDS  = (TM / 2) * SX_STRIDE;   // 64 * 516 = 33024
constexpr int SW_STRIDE = 516;            // words per dup'd codebook col
constexpr int SW_WORDS  = TK * SW_STRIDE;         // 32 * 516 = 16512
constexpr int SMEM_BYTES = (SX_WORDS + SW_WORDS) * 4;  // 198144 B

// ----- scratch (device globals; no allocations allowed) -----
__device__ float g_xsq[Nrows];
__device__ float g_wsq[Kc];
__device__ float g_dw[Kc * Dc];
__device__ float g_counts[Kc];
__device__ float g_loss;

// ---------------------------------------------------------------------------
// Kernel 0: row sum-of-squares for x and w; zero scatter scratch.
// UNCHANGED from round 2 -> xsq/wsq bit-identical -> argmin bit-identical.
// ---------------------------------------------------------------------------
__global__ void prep_kernel(const float* __restrict__ x,
                            const float* __restrict__ w) {
  int b = blockIdx.x;
  int t = threadIdx.x;
  float v;
  if (b < Nrows) {
    v = x[(size_t)b * Dc + t];
  } else {
    int k = b - Nrows;
    v = w[(size_t)k * Dc + t];
    g_dw[(size_t)k * Dc + t] = 0.0f;
    if (t == 0) g_counts[k] = 0.0f;
    if (t == 1 && k == 0) g_loss = 0.0f;
  }
  float s = v * v;
  #pragma unroll
  for (int o = 16; o; o >>= 1) s += __shfl_down_sync(0xffffffffu, s, o);
  __shared__ float red[8];
  if ((t & 31) == 0) red[t >> 5] = s;
  __syncthreads();
  if (t == 0) {
    float tot = red[0];
    #pragma unroll
    for (int i = 1; i < 8; i++) tot += red[i];
    if (b < Nrows) g_xsq[b] = tot;
    else           g_wsq[b - Nrows] = tot;
  }
}

// ---------------------------------------------------------------------------
// Kernel 1: fused distance GEMM + argmin + gather/scatter epilogue.
//   score[n,k] = fp32( fp32(xsq[n] + wsq[k]) - 2 * dot(x[n], w[k]) )
// dot accumulation: single fp32x2 accumulator per (n,k), d ascending ->
// bit-identical to the round-2 kernel. Tie -> lowest k.
// Block: 128 rows, 32 codebook cols per chunk (dup'd in smem), 256 threads.
// Microtile: 4 row-pairs x 2 cols per thread.
// ---------------------------------------------------------------------------
__global__ void __launch_bounds__(256, 1)
argmin_kernel(const float* __restrict__ x, const float* __restrict__ w,
              float* __restrict__ outQ) {
  extern __shared__ float smem[];
  float* sx = smem;                 // x tile, pair-packed (x0[d],x1[d]) at 2d
  float* sw = smem + SX_WORDS;      // w chunk, duplicated (w[d],w[d]) at 2d

  const int tid = threadIdx.x;
  const int tm = tid & 15;          // row-pair group (pairs tm, tm+16, +32, +48)
  const int tk = tid >> 4;          // col group (cols tk, tk+16)
  const int rowBase = blockIdx.x * TM;

  // ---- load x tile: sx[pr*516 + par + 2*d] = x[rowBase + 2*pr + par][d]
  {
    int r    = tid >> 1;            // 0..127
    int half = tid & 1;             // which 128-d half
    int pr   = r >> 1, par = r & 1;
    const float4* src =
        reinterpret_cast<const float4*>(x + (size_t)(rowBase + r) * Dc) + half * 32;
    float* dst = sx + pr * SX_STRIDE + par;
    #pragma unroll
    for (int q = 0; q < 32; q++) {
      float4 v = src[q];
      int d = half * 128 + q * 4;
      dst[2 * d + 0] = v.x;
      dst[2 * d + 2] = v.y;
      dst[2 * d + 4] = v.z;
      dst[2 * d + 6] = v.w;
    }
  }

  float xsqv[8];
  float best[8];
  int   bidx[8];
  #pragma unroll
  for (int i = 0; i < 4; i++) {
    int pr = tm + 16 * i;
    xsqv[2 * i + 0] = g_xsq[rowBase + 2 * pr + 0];
    xsqv[2 * i + 1] = g_xsq[rowBase + 2 * pr + 1];
    best[2 * i] = best[2 * i + 1] = 3.4e38f;
    bidx[2 * i] = bidx[2 * i + 1] = 0;
  }

  const float* ax0 = sx + (tm + 0)  * SX_STRIDE;
  const float* ax1 = sx + (tm + 16) * SX_STRIDE;
  const float* ax2 = sx + (tm + 32) * SX_STRIDE;
  const float* ax3 = sx + (tm + 48) * SX_STRIDE;
  const float* bw0 = sw + (tk + 0)  * SW_STRIDE;
  const float* bw1 = sw + (tk + 16) * SW_STRIDE;

  for (int ck = 0; ck < NCHUNKS; ck++) {
    __syncthreads();   // previous chunk compute done (and x-tile stores on ck=0)
    // ---- load w chunk, DUPLICATED: sw[col*516 + 2d + {0,1}] = w[ck*32+col][d]
    {
      int col = tid >> 3, seg = tid & 7;   // col 0..31, seg covers 32 d's
      const float4* src =
          reinterpret_cast<const float4*>(w + (size_t)(ck * TK + col) * Dc) + seg * 8;
      float* dst = sw + col * SW_STRIDE + seg * 64;
      #pragma unroll
      for (int q = 0; q < 8; q++) {
        float4 v = src[q];
        float4 d0 = make_float4(v.x, v.x, v.y, v.y);
        float4 d1 = make_float4(v.z, v.z, v.w, v.w);
        *reinterpret_cast<float4*>(dst + 8 * q)     = d0;
        *reinterpret_cast<float4*>(dst + 8 * q + 4) = d1;
      }
    }
    __syncthreads();

    unsigned long long acc[4][2];
    #pragma unroll
    for (int i = 0; i < 4; i++) { acc[i][0] = 0ull; acc[i][1] = 0ull; }

    #pragma unroll 8
    for (int d = 0; d < Dc; d += 2) {
      ulonglong2 a0 = *reinterpret_cast<const ulonglong2*>(ax0 + 2 * d);
      ulonglong2 a1 = *reinterpret_cast<const ulonglong2*>(ax1 + 2 * d);
      ulonglong2 a2 = *reinterpret_cast<const ulonglong2*>(ax2 + 2 * d);
      ulonglong2 a3 = *reinterpret_cast<const ulonglong2*>(ax3 + 2 * d);
      ulonglong2 b0 = *reinterpret_cast<const ulonglong2*>(bw0 + 2 * d);
      ulonglong2 b1 = *reinterpret_cast<const ulonglong2*>(bw1 + 2 * d);
      // d (then d+1), each col j, each pair i — d-ascending per accumulator
      asm("fma.rn.f32x2 %0, %1, %2, %0;" : "+l"(acc[0][0]) : "l"(a0.x), "l"(b0.x));
      asm("fma.rn.f32x2 %0, %1, %2, %0;" : "+l"(acc[1][0]) : "l"(a1.x), "l"(b0.x));
      asm("fma.rn.f32x2 %0, %1, %2, %0;" : "+l"(acc[2][0]) : "l"(a2.x), "l"(b0.x));
      asm("fma.rn.f32x2 %0, %1, %2, %0;" : "+l"(acc[3][0]) : "l"(a3.x), "l"(b0.x));
      asm("fma.rn.f32x2 %0, %1, %2, %0;" : "+l"(acc[0][1]) : "l"(a0.x), "l"(b1.x));
      asm("fma.rn.f32x2 %0, %1, %2, %0;" : "+l"(acc[1][1]) : "l"(a1.x), "l"(b1.x));
      asm("fma.rn.f32x2 %0, %1, %2, %0;" : "+l"(acc[2][1]) : "l"(a2.x), "l"(b1.x));
      asm("fma.rn.f32x2 %0, %1, %2, %0;" : "+l"(acc[3][1]) : "l"(a3.x), "l"(b1.x));
      asm("fma.rn.f32x2 %0, %1, %2, %0;" : "+l"(acc[0][0]) : "l"(a0.y), "l"(b0.y));
      asm("fma.rn.f32x2 %0, %1, %2, %0;" : "+l"(acc[1][0]) : "l"(a1.y), "l"(b0.y));
      asm("fma.rn.f32x2 %0, %1, %2, %0;" : "+l"(acc[2][0]) : "l"(a2.y), "l"(b0.y));
      asm("fma.rn.f32x2 %0, %1, %2, %0;" : "+l"(acc[3][0]) : "l"(a3.y), "l"(b0.y));
      asm("fma.rn.f32x2 %0, %1, %2, %0;" : "+l"(acc[0][1]) : "l"(a0.y), "l"(b1.y));
      asm("fma.rn.f32x2 %0, %1, %2, %0;" : "+l"(acc[1][1]) : "l"(a1.y), "l"(b1.y));
      asm("fma.rn.f32x2 %0, %1, %2, %0;" : "+l"(acc[2][1]) : "l"(a2.y), "l"(b1.y));
      asm("fma.rn.f32x2 %0, %1, %2, %0;" : "+l"(acc[3][1]) : "l"(a3.y), "l"(b1.y));
    }

    // ---- scores + running argmin (same fadd chain as round 2)
    #pragma unroll
    for (int j = 0; j < 2; j++) {
      int c = ck * TK + tk + 16 * j;
      float wsqc = g_wsq[c];
      #pragma unroll
      for (int i = 0; i < 4; i++) {
        float2 dv = *reinterpret_cast<float2*>(&acc[i][j]);
        float r1a = __fadd_rn(xsqv[2 * i + 0], wsqc);
        float s0  = __fadd_rn(r1a, -2.0f * dv.x);
        float r1b = __fadd_rn(xsqv[2 * i + 1], wsqc);
        float s1  = __fadd_rn(r1b, -2.0f * dv.y);
        if (s0 < best[2 * i + 0]) { best[2 * i + 0] = s0; bidx[2 * i + 0] = c; }
        if (s1 < best[2 * i + 1]) { best[2 * i + 1] = s1; bidx[2 * i + 1] = c; }
      }
    }
  }

  // ---- cross-thread (over tk) argmin reduction; reuse sw region
  __syncthreads();
  float* sMin = sw;                             // [16][128]
  int*   sIdx = reinterpret_cast<int*>(sw + 16 * 128);
  int*   sFin = reinterpret_cast<int*>(sw) + 4096;   // final idx per row [128]
  #pragma unroll
  for (int i = 0; i < 4; i++) {
    #pragma unroll
    for (int p = 0; p < 2; p++) {
      int r = 2 * (tm + 16 * i) + p;
      sMin[tk * 128 + r] = best[2 * i + p];
      sIdx[tk * 128 + r] = bidx[2 * i + p];
    }
  }
  __syncthreads();
  if (tid < 128) {
    float bv = sMin[tid];
    int   bi = sIdx[tid];
    #pragma unroll
    for (int t2 = 1; t2 < 16; t2++) {
      float v = sMin[t2 * 128 + tid];
      int   ii = sIdx[t2 * 128 + tid];
      if (v < bv || (v == bv && ii < bi)) { bv = v; bi = ii; }
    }
    sFin[tid] = bi;
    atomicAdd(&g_counts[bi], 1.0f);
  }
  __syncthreads();

  // ---- epilogue: gather quantized rows, loss partial, dw scatter.
  // x is still resident in sx. 256 threads x 32 iters cover 128 rows x 64 quads.
  float lsum = 0.0f;
  {
    int q = tid & 63, rg = tid >> 6;
    #pragma unroll 4
    for (int it = 0; it < 32; ++it) {
      int row = rg * 32 + it;
      int k = sFin[row];
      float4 wv = *reinterpret_cast<const float4*>(w + (size_t)k * Dc + 4 * q);
      int pr = row >> 1, par = row & 1;
      const float* xs = sx + pr * SX_STRIDE + par + 8 * q;
      float x0 = xs[0], x1 = xs[2], x2 = xs[4], x3 = xs[6];
      *reinterpret_cast<float4*>(outQ + (size_t)(rowBase + row) * Dc + 4 * q) = wv;
      float d0 = x0 - wv.x, d1 = x1 - wv.y, d2 = x2 - wv.z, d3 = x3 - wv.w;
      lsum += d0 * d0 + d1 * d1 + d2 * d2 + d3 * d3;
      float* dwp = g_dw + (size_t)k * Dc + 4 * q;
      atomicAdd(dwp + 0, x0);
      atomicAdd(dwp + 1, x1);
      atomicAdd(dwp + 2, x2);
      atomicAdd(dwp + 3, x3);
    }
  }
  #pragma unroll
  for (int o = 16; o; o >>= 1) lsum += __shfl_down_sync(0xffffffffu, lsum, o);
  __shared__ float red2[8];
  if ((tid & 31) == 0) red2[tid >> 5] = lsum;
  __syncthreads();
  if (tid == 0) {
    float tot = red2[0];
    #pragma unroll
    for (int i = 1; i < 8; i++) tot += red2[i];
    atomicAdd(&g_loss, tot);
  }
}

// ---------------------------------------------------------------------------
// Kernel 2: fused cluster-size EMA + Laplace smoothing + ema_w EMA + embed.
// grid = Kc blocks (one per k), 256 threads (one per d).
// n = sum(cs) = 0.99*sum(ema_cs) + 0.01*sum(counts); sum(counts) == Nrows exact.
// ---------------------------------------------------------------------------
__global__ void emacs_kernel(const float* __restrict__ ema_cs,
                             const float* __restrict__ ema_w,
                             float* __restrict__ outLoss,
                             float* __restrict__ outEmbed,
                             float* __restrict__ outCS,
                             float* __restrict__ outEmaW) {
  int k = blockIdx.x, d = threadIdx.x;
  __shared__ float red[8];
  __shared__ float s_cs;

  // redundant per-block reduce of sum(ema_cs) (1024 floats)
  float4 v = reinterpret_cast<const float4*>(ema_cs)[d];
  float s = v.x + v.y + v.z + v.w;
  #pragma unroll
  for (int o = 16; o; o >>= 1) s += __shfl_down_sync(0xffffffffu, s, o);
  if ((d & 31) == 0) red[d >> 5] = s;
  __syncthreads();
  if (d == 0) {
    float S = red[0];
    #pragma unroll
    for (int i = 1; i < 8; i++) S += red[i];
    float n = DECAYF * S + OMDF * (float)Nrows;
    float c = ema_cs[k] * DECAYF + OMDF * g_counts[k];
    float csf = (c + EPSF) / (n + KEPSF) * n;
    s_cs = csf;
    outCS[k] = csf;
    if (k == 0) outLoss[0] = 0.25f * g_loss * (1.0f / 4194304.0f);
  }
  __syncthreads();
  float csv = s_cs;
  size_t i = (size_t)k * Dc + d;
  float ew = ema_w[i] * DECAYF + OMDF * g_dw[i];
  outEmaW[i]  = ew;
  outEmbed[i] = ew / csv;
}

// ---------------------------------------------------------------------------
extern "C" void kernel_launch(void* const* d_in, const int* in_sizes, int n_in,
                              void* d_out, int out_size) {
  const float* x      = (const float*)d_in[0];
  const float* w      = (const float*)d_in[1];
  const float* ema_cs = (const float*)d_in[2];
  const float* ema_w  = (const float*)d_in[3];

  float* out      = (float*)d_out;
  float* outQ     = out;                                   // 4,194,304
  float* outLoss  = out + (size_t)Nrows * Dc;              // 1
  float* outEmbed = outLoss + 1;                           // 262,144
  float* outCS    = outEmbed + (size_t)Kc * Dc;            // 1,024
  float* outEmaW  = outCS + Kc;                            // 262,144

  cudaFuncSetAttribute(argmin_kernel,
                       cudaFuncAttributeMaxDynamicSharedMemorySize, SMEM_BYTES);

  prep_kernel<<<Nrows + Kc, 256>>>(x, w);
  argmin_kernel<<<Nrows / TM, 256, SMEM_BYTES>>>(x, w, outQ);
  emacs_kernel<<<Kc, 256>>>(ema_cs, ema_w, outLoss, outEmbed, outCS, outEmaW);
}

// round 5
// speedup vs baseline: 1.7767x; 1.7767x over previous
#include <cuda_runtime.h>

// ---------------------------------------------------------------------------
// VQ-EMA layer, GB300 (sm_103a)  — round 4
// Inputs : x [16,1024,256] f32, embed_w [1024,256] f32,
//          ema_cluster_size [1024] f32, ema_w [1024,256] f32
// Output : concat( quantized[16*1024*256], loss[1], embed_new[1024*256],
//                  cs[1024], ema_w_new[1024*256] )
// ---------------------------------------------------------------------------

constexpr int Bc = 16, Tc = 1024, Dc = 256, Kc = 1024;
constexpr int Nrows = Bc * Tc;            // 16384
constexpr int TM = 128;                   // rows per block
constexpr int TK = 64;                    // codebook cols per chunk
constexpr int NCHUNKS = Kc / TK;          // 16

constexpr float DECAYF = 0.99f;
constexpr float OMDF   = 0.01f;
constexpr float EPSF   = 1e-5f;
constexpr float KEPSF  = 0.01024f;        // K * EPS

// smem layout (words) for argmin kernel
constexpr int SX_STRIDE = 514;            // words per row-pair (2*256 + 2 pad); 514%32==2 -> conflict-free a
constexpr int SX_WORDS  = (TM / 2) * SX_STRIDE;   // 64 * 514 = 32896
constexpr int SW_STRIDE = 260;            // words per codebook col; %4==0 -> aligned float2/float4
constexpr int SW_WORDS  = TK * SW_STRIDE;         // 64 * 260 = 16640
constexpr int SMEM_BYTES = (SX_WORDS + SW_WORDS) * 4;  // 198144 B

// ----- scratch (device globals; no allocations allowed) -----
__device__ float g_xsq[Nrows];
__device__ float g_wsq[Kc];
__device__ float g_dw[Kc * Dc];
__device__ float g_counts[Kc];
__device__ float g_loss;

// ---------------------------------------------------------------------------
// Kernel 0: row sum-of-squares for x and w; zero scatter scratch.
// BYTE-IDENTICAL to rounds 2/3 -> xsq/wsq bit-identical -> argmin bit-identical.
// ---------------------------------------------------------------------------
__global__ void prep_kernel(const float* __restrict__ x,
                            const float* __restrict__ w) {
  int b = blockIdx.x;
  int t = threadIdx.x;
  float v;
  if (b < Nrows) {
    v = x[(size_t)b * Dc + t];
  } else {
    int k = b - Nrows;
    v = w[(size_t)k * Dc + t];
    g_dw[(size_t)k * Dc + t] = 0.0f;
    if (t == 0) g_counts[k] = 0.0f;
    if (t == 1 && k == 0) g_loss = 0.0f;
  }
  float s = v * v;
  #pragma unroll
  for (int o = 16; o; o >>= 1) s += __shfl_down_sync(0xffffffffu, s, o);
  __shared__ float red[8];
  if ((t & 31) == 0) red[t >> 5] = s;
  __syncthreads();
  if (t == 0) {
    float tot = red[0];
    #pragma unroll
    for (int i = 1; i < 8; i++) tot += red[i];
    if (b < Nrows) g_xsq[b] = tot;
    else           g_wsq[b - Nrows] = tot;
  }
}

// ---------------------------------------------------------------------------
// Kernel 1: fused distance GEMM + argmin + gather/scatter epilogue.
//   score[n,k] = fp32( fp32(xsq[n] + wsq[k]) - 2 * dot(x[n], w[k]) )
// dot: single fp32x2 accumulator per (n,k), d ascending -> bit-identical to
// rounds 2/3. Tie -> lowest k.
// Block: 128 rows x 64 cols/chunk, 256 threads, microtile 4 row-pairs x 4 cols.
// a: LDS.64 pair-packed (stride 514, conflict-free).
// b: LDS.64 over two d's (stride 260, broadcast), MOV-duplicated into pairs.
// ---------------------------------------------------------------------------
__global__ void __launch_bounds__(256, 1)
argmin_kernel(const float* __restrict__ x, const float* __restrict__ w,
              float* __restrict__ outQ) {
  extern __shared__ float smem[];
  float* sx = smem;                 // x tile, pair-packed (x0[d],x1[d]) at 2d
  float* sw = smem + SX_WORDS;      // w chunk, col-major

  const int tid = threadIdx.x;
  const int tm = tid & 15;          // row-pair group (pairs tm, tm+16, +32, +48)
  const int tk = tid >> 4;          // col group (cols tk, tk+16, +32, +48)
  const int rowBase = blockIdx.x * TM;

  // ---- load x tile: sx[pr*514 + par + 2*d] = x[rowBase + 2*pr + par][d]
  {
    int r    = tid >> 1;            // 0..127
    int half = tid & 1;             // which 128-d half
    int pr   = r >> 1, par = r & 1;
    const float4* src =
        reinterpret_cast<const float4*>(x + (size_t)(rowBase + r) * Dc) + half * 32;
    float* dst = sx + pr * SX_STRIDE + par;
    #pragma unroll
    for (int q = 0; q < 32; q++) {
      float4 v = src[q];
      int d = half * 128 + q * 4;
      dst[2 * d + 0] = v.x;
      dst[2 * d + 2] = v.y;
      dst[2 * d + 4] = v.z;
      dst[2 * d + 6] = v.w;
    }
  }

  float xsqv[8];
  float best[8];
  int   bidx[8];
  #pragma unroll
  for (int i = 0; i < 4; i++) {
    int pr = tm + 16 * i;
    xsqv[2 * i + 0] = g_xsq[rowBase + 2 * pr + 0];
    xsqv[2 * i + 1] = g_xsq[rowBase + 2 * pr + 1];
    best[2 * i] = best[2 * i + 1] = 3.4e38f;
    bidx[2 * i] = bidx[2 * i + 1] = 0;
  }

  const float* ax0 = sx + (tm + 0)  * SX_STRIDE;
  const float* ax1 = sx + (tm + 16) * SX_STRIDE;
  const float* ax2 = sx + (tm + 32) * SX_STRIDE;
  const float* ax3 = sx + (tm + 48) * SX_STRIDE;
  const float* bw0 = sw + (tk + 0)  * SW_STRIDE;
  const float* bw1 = sw + (tk + 16) * SW_STRIDE;
  const float* bw2 = sw + (tk + 32) * SW_STRIDE;
  const float* bw3 = sw + (tk + 48) * SW_STRIDE;

  for (int ck = 0; ck < NCHUNKS; ck++) {
    __syncthreads();   // previous chunk compute done (and x-tile stores on ck=0)
    // ---- load w chunk col-major: sw[col*260 + d] = w[ck*64 + col][d]
    {
      int col = tid >> 2, dseg = tid & 3;
      const float4* src =
          reinterpret_cast<const float4*>(w + (size_t)(ck * TK + col) * Dc) + dseg * 16;
      float* dst = sw + col * SW_STRIDE + dseg * 64;
      #pragma unroll
      for (int q = 0; q < 16; q++) {
        *reinterpret_cast<float4*>(dst + 4 * q) = src[q];
      }
    }
    __syncthreads();

    unsigned long long acc[4][4];
    #pragma unroll
    for (int i = 0; i < 4; i++)
      #pragma unroll
      for (int j = 0; j < 4; j++) acc[i][j] = 0ull;  // packed (0.f, 0.f)

    #pragma unroll 4
    for (int d = 0; d < Dc; d += 2) {
      // a: 4 row-pairs x 2 d's, LDS.64 each (conflict-free, stride 514)
      unsigned long long a0[4], a1[4];
      a0[0] = *reinterpret_cast<const unsigned long long*>(ax0 + 2 * d);
      a0[1] = *reinterpret_cast<const unsigned long long*>(ax1 + 2 * d);
      a0[2] = *reinterpret_cast<const unsigned long long*>(ax2 + 2 * d);
      a0[3] = *reinterpret_cast<const unsigned long long*>(ax3 + 2 * d);
      a1[0] = *reinterpret_cast<const unsigned long long*>(ax0 + 2 * d + 2);
      a1[1] = *reinterpret_cast<const unsigned long long*>(ax1 + 2 * d + 2);
      a1[2] = *reinterpret_cast<const unsigned long long*>(ax2 + 2 * d + 2);
      a1[3] = *reinterpret_cast<const unsigned long long*>(ax3 + 2 * d + 2);
      // b: 4 cols x (d, d+1) as one LDS.64 each (broadcast), then dup to pairs
      uint2 bv[4];
      bv[0] = *reinterpret_cast<const uint2*>(bw0 + d);
      bv[1] = *reinterpret_cast<const uint2*>(bw1 + d);
      bv[2] = *reinterpret_cast<const uint2*>(bw2 + d);
      bv[3] = *reinterpret_cast<const uint2*>(bw3 + d);
      unsigned long long b0[4], b1[4];
      #pragma unroll
      for (int j = 0; j < 4; j++) {
        asm("mov.b64 %0, {%1, %1};" : "=l"(b0[j]) : "r"(bv[j].x));
        asm("mov.b64 %0, {%1, %1};" : "=l"(b1[j]) : "r"(bv[j].y));
      }
      // d first (all accs), then d+1 -> per-accumulator d ascending (bit-exact)
      #pragma unroll
      for (int i = 0; i < 4; i++) {
        #pragma unroll
        for (int j = 0; j < 4; j++) {
          asm("fma.rn.f32x2 %0, %1, %2, %0;"
              : "+l"(acc[i][j]) : "l"(a0[i]), "l"(b0[j]));
        }
      }
      #pragma unroll
      for (int i = 0; i < 4; i++) {
        #pragma unroll
        for (int j = 0; j < 4; j++) {
          asm("fma.rn.f32x2 %0, %1, %2, %0;"
              : "+l"(acc[i][j]) : "l"(a1[i]), "l"(b1[j]));
        }
      }
    }

    // ---- scores + running argmin (same fadd chain as rounds 2/3)
    #pragma unroll
    for (int j = 0; j < 4; j++) {
      int c = ck * TK + tk + 16 * j;
      float wsqc = g_wsq[c];
      #pragma unroll
      for (int i = 0; i < 4; i++) {
        float2 dv = *reinterpret_cast<float2*>(&acc[i][j]);
        float r1a = __fadd_rn(xsqv[2 * i + 0], wsqc);
        float s0  = __fadd_rn(r1a, -2.0f * dv.x);
        float r1b = __fadd_rn(xsqv[2 * i + 1], wsqc);
        float s1  = __fadd_rn(r1b, -2.0f * dv.y);
        if (s0 < best[2 * i + 0]) { best[2 * i + 0] = s0; bidx[2 * i + 0] = c; }
        if (s1 < best[2 * i + 1]) { best[2 * i + 1] = s1; bidx[2 * i + 1] = c; }
      }
    }
  }

  // ---- cross-thread (over tk) argmin reduction; reuse sw region
  __syncthreads();
  float* sMin = sw;                             // [16][128]
  int*   sIdx = reinterpret_cast<int*>(sw + 16 * 128);
  int*   sFin = reinterpret_cast<int*>(sw) + 4096;   // final idx per row [128]
  #pragma unroll
  for (int i = 0; i < 4; i++) {
    #pragma unroll
    for (int p = 0; p < 2; p++) {
      int r = 2 * (tm + 16 * i) + p;
      sMin[tk * 128 + r] = best[2 * i + p];
      sIdx[tk * 128 + r] = bidx[2 * i + p];
    }
  }
  __syncthreads();
  if (tid < 128) {
    float bv = sMin[tid];
    int   bi = sIdx[tid];
    #pragma unroll
    for (int t2 = 1; t2 < 16; t2++) {
      float v = sMin[t2 * 128 + tid];
      int   ii = sIdx[t2 * 128 + tid];
      if (v < bv || (v == bv && ii < bi)) { bv = v; bi = ii; }
    }
    sFin[tid] = bi;
    atomicAdd(&g_counts[bi], 1.0f);
  }
  __syncthreads();

  // ---- epilogue: gather quantized rows, loss partial, dw scatter.
  // x is still resident in sx. 256 threads x 32 iters cover 128 rows x 64 quads.
  float lsum = 0.0f;
  {
    int q = tid & 63, rg = tid >> 6;
    #pragma unroll 4
    for (int it = 0; it < 32; ++it) {
      int row = rg * 32 + it;
      int k = sFin[row];
      float4 wv = *reinterpret_cast<const float4*>(w + (size_t)k * Dc + 4 * q);
      int pr = row >> 1, par = row & 1;
      const float* xs = sx + pr * SX_STRIDE + par + 8 * q;
      float x0 = xs[0], x1 = xs[2], x2 = xs[4], x3 = xs[6];
      *reinterpret_cast<float4*>(outQ + (size_t)(rowBase + row) * Dc + 4 * q) = wv;
      float d0 = x0 - wv.x, d1 = x1 - wv.y, d2 = x2 - wv.z, d3 = x3 - wv.w;
      lsum += d0 * d0 + d1 * d1 + d2 * d2 + d3 * d3;
      float* dwp = g_dw + (size_t)k * Dc + 4 * q;
      atomicAdd(dwp + 0, x0);
      atomicAdd(dwp + 1, x1);
      atomicAdd(dwp + 2, x2);
      atomicAdd(dwp + 3, x3);
    }
  }
  #pragma unroll
  for (int o = 16; o; o >>= 1) lsum += __shfl_down_sync(0xffffffffu, lsum, o);
  __shared__ float red2[8];
  if ((tid & 31) == 0) red2[tid >> 5] = lsum;
  __syncthreads();
  if (tid == 0) {
    float tot = red2[0];
    #pragma unroll
    for (int i = 1; i < 8; i++) tot += red2[i];
    atomicAdd(&g_loss, tot);
  }
}

// ---------------------------------------------------------------------------
// Kernel 2: fused cluster-size EMA + Laplace smoothing + ema_w EMA + embed.
// grid = Kc blocks (one per k), 256 threads (one per d).
// n = 0.99*sum(ema_cs) + 0.01*Nrows  (sum(counts) == Nrows exactly).
// ---------------------------------------------------------------------------
__global__ void emacs_kernel(const float* __restrict__ ema_cs,
                             const float* __restrict__ ema_w,
                             float* __restrict__ outLoss,
                             float* __restrict__ outEmbed,
                             float* __restrict__ outCS,
                             float* __restrict__ outEmaW) {
  int k = blockIdx.x, d = threadIdx.x;
  __shared__ float red[8];
  __shared__ float s_cs;

  // redundant per-block reduce of sum(ema_cs) (1024 floats)
  float4 v = reinterpret_cast<const float4*>(ema_cs)[d];
  float s = v.x + v.y + v.z + v.w;
  #pragma unroll
  for (int o = 16; o; o >>= 1) s += __shfl_down_sync(0xffffffffu, s, o);
  if ((d & 31) == 0) red[d >> 5] = s;
  __syncthreads();
  if (d == 0) {
    float S = red[0];
    #pragma unroll
    for (int i = 1; i < 8; i++) S += red[i];
    float n = DECAYF * S + OMDF * (float)Nrows;
    float c = ema_cs[k] * DECAYF + OMDF * g_counts[k];
    float csf = (c + EPSF) / (n + KEPSF) * n;
    s_cs = csf;
    outCS[k] = csf;
    if (k == 0) outLoss[0] = 0.25f * g_loss * (1.0f / 4194304.0f);
  }
  __syncthreads();
  float csv = s_cs;
  size_t i = (size_t)k * Dc + d;
  float ew = ema_w[i] * DECAYF + OMDF * g_dw[i];
  outEmaW[i]  = ew;
  outEmbed[i] = ew / csv;
}

// ---------------------------------------------------------------------------
extern "C" void kernel_launch(void* const* d_in, const int* in_sizes, int n_in,
                              void* d_out, int out_size) {
  const float* x      = (const float*)d_in[0];
  const float* w      = (const float*)d_in[1];
  const float* ema_cs = (const float*)d_in[2];
  const float* ema_w  = (const float*)d_in[3];

  float* out      = (float*)d_out;
  float* outQ     = out;                                   // 4,194,304
  float* outLoss  = out + (size_t)Nrows * Dc;              // 1
  float* outEmbed = outLoss + 1;                           // 262,144
  float* outCS    = outEmbed + (size_t)Kc * Dc;            // 1,024
  float* outEmaW  = outCS + Kc;                            // 262,144

  cudaFuncSetAttribute(argmin_kernel,
                       cudaFuncAttributeMaxDynamicSharedMemorySize, SMEM_BYTES);

  prep_kernel<<<Nrows + Kc, 256>>>(x, w);
  argmin_kernel<<<Nrows / TM, 256, SMEM_BYTES>>>(x, w, outQ);
  emacs_kernel<<<Kc, 256>>>(ema_cs, ema_w, outLoss, outEmbed, outCS, outEmaW);
}